// round 15
// baseline (speedup 1.0000x reference)
#include <cuda_runtime.h>
#include <cuda_fp16.h>
#include <cstdint>

// ---------------- smem layout (bytes) ----------------
#define STG_STRIDE 144                      // fp32 staging row: 128B data + 16B pad (16B-mult!)
#define STG_BYTES  (128 * 144)              // 18432; 2 buffers at 0
// post-layer0: ACT (128 x 272 = 34816) aliases the STG region [0, 36864)
#define ACT_STRIDE 272
#define A16_BASE   (2 * STG_BYTES)          // 36864: layer-0 fp16 A chunks, 2 bufs
#define A16_BYTES  (128 * 80)               // 10240
#define B_BASE     (A16_BASE + 2 * A16_BYTES)   // 57344: layer-0 B ring, 3 stages
#define BB_BYTES   (128 * 80)               // 10240
// post-layer0: WBUF (34816) aliases [A16_BASE, A16_BASE+34816)
#define WBUF_BASE  A16_BASE
#define MISC_BASE  (B_BASE + 3 * BB_BYTES)  // 88064
#define SMEM_BYTES (MISC_BASE + 2560)       // 90624  (2 CTAs/SM)

// ---------------- device scratch ----------------
__device__ __half g_W0h[128 * 384];  // [n][k] fp16 W0^T (k = 0..383)
__device__ __half g_W1h[128 * 128];  // [n][k] fp16( a0[k] * W1[k][n] )
__device__ __half g_W2h[128 * 128];  // [n][k] fp16( a1[k] * W2[k][n] )
__device__ float  g_U[64 * 128];     // U'[b][n] = b0[n] + u[b]@W0[384:,n]
__device__ float  g_b1p[128];
__device__ float  g_b2p[128];
__device__ float  g_a2v[128];
__device__ float  g_c2v[128];

// ---------------- helpers ----------------
__device__ __forceinline__ uint32_t smem_u32(const void* p) {
    uint32_t a;
    asm("{ .reg .u64 t; cvta.to.shared.u64 t, %1; cvt.u32.u64 %0, t; }" : "=r"(a) : "l"(p));
    return a;
}
__device__ __forceinline__ void cp16(void* dst, const void* src) {
    uint32_t sa = smem_u32(dst);
    asm volatile("cp.async.cg.shared.global [%0], [%1], 16;" :: "r"(sa), "l"(src) : "memory");
}
#define CPC asm volatile("cp.async.commit_group;" ::: "memory")
#define CPW(n) asm volatile("cp.async.wait_group %0;" :: "n"(n) : "memory")

__device__ __forceinline__ void ldsm4(uint32_t& r0, uint32_t& r1, uint32_t& r2, uint32_t& r3,
                                      uint32_t addr) {
    asm volatile("ldmatrix.sync.aligned.m8n8.x4.shared.b16 {%0,%1,%2,%3}, [%4];"
                 : "=r"(r0), "=r"(r1), "=r"(r2), "=r"(r3) : "r"(addr));
}
__device__ __forceinline__ void mma16816(float* c, const uint32_t* a, uint32_t b0, uint32_t b1) {
    asm volatile(
        "mma.sync.aligned.m16n8k16.row.col.f32.f16.f16.f32 "
        "{%0,%1,%2,%3}, {%4,%5,%6,%7}, {%8,%9}, {%0,%1,%2,%3};"
        : "+f"(c[0]), "+f"(c[1]), "+f"(c[2]), "+f"(c[3])
        : "r"(a[0]), "r"(a[1]), "r"(a[2]), "r"(a[3]), "r"(b0), "r"(b1));
}
__device__ __forceinline__ uint32_t h2u(__half2 h) {
    union { __half2 h; uint32_t u; } cv;
    cv.h = h;
    return cv.u;
}

// ---------------- prep kernels ----------------
__global__ void prep_weights(const float* __restrict__ W0, const float* __restrict__ W1,
                             const float* __restrict__ W2,
                             const float* __restrict__ g0, const float* __restrict__ v0,
                             const float* __restrict__ g1, const float* __restrict__ v1) {
    int i = blockIdx.x * 256 + threadIdx.x;
    if (i < 49152) {
        int n = i / 384, k = i - n * 384;
        g_W0h[i] = __float2half(W0[k * 128 + n]);
    } else if (i < 65536) {
        int j = i - 49152;
        int n = j >> 7, k = j & 127;
        float a0 = g0[k] * rsqrtf(v0[k] + 1e-5f);
        g_W1h[j] = __float2half(a0 * W1[k * 128 + n]);
    } else if (i < 81920) {
        int j = i - 65536;
        int n = j >> 7, k = j & 127;
        float a1 = g1[k] * rsqrtf(v1[k] + 1e-5f);
        g_W2h[j] = __float2half(a1 * W2[k * 128 + n]);
    }
}

__global__ void prep_bias(const float* __restrict__ W1, const float* __restrict__ b1,
                          const float* __restrict__ W2, const float* __restrict__ b2,
                          const float* __restrict__ g0, const float* __restrict__ be0,
                          const float* __restrict__ m0, const float* __restrict__ v0,
                          const float* __restrict__ g1, const float* __restrict__ be1,
                          const float* __restrict__ m1, const float* __restrict__ v1,
                          const float* __restrict__ g2, const float* __restrict__ be2,
                          const float* __restrict__ m2, const float* __restrict__ v2) {
    __shared__ float r1[128], r2[128];
    const int n = blockIdx.x, k = threadIdx.x;
    float a0 = g0[k] * rsqrtf(v0[k] + 1e-5f);
    float c0 = be0[k] - m0[k] * a0;
    float a1 = g1[k] * rsqrtf(v1[k] + 1e-5f);
    float c1 = be1[k] - m1[k] * a1;
    r1[k] = c0 * W1[k * 128 + n];
    r2[k] = c1 * W2[k * 128 + n];
    __syncthreads();
    for (int off = 64; off; off >>= 1) {
        if (k < off) { r1[k] += r1[k + off]; r2[k] += r2[k + off]; }
        __syncthreads();
    }
    if (k == 0) {
        g_b1p[n] = b1[n] + r1[0];
        g_b2p[n] = b2[n] + r2[0];
        float a2 = g2[n] * rsqrtf(v2[n] + 1e-5f);
        g_a2v[n] = a2;
        g_c2v[n] = be2[n] - m2[n] * a2;
    }
}

__global__ void prep_U(const float* __restrict__ u, const float* __restrict__ W0,
                       const float* __restrict__ b0) {
    __shared__ float ub[128];
    int b = blockIdx.x, n = threadIdx.x;
    ub[n] = u[b * 128 + n];
    __syncthreads();
    float acc = b0[n];
    for (int k = 0; k < 128; k++) acc += ub[k] * W0[(384 + k) * 128 + n];
    g_U[b * 128 + n] = acc;
}

// ---------------- main kernel ----------------
__global__ void __launch_bounds__(256, 2)
megnet_main(const float* __restrict__ src, const float* __restrict__ dst_,
            const float* __restrict__ edg, const int* __restrict__ batch,
            float* __restrict__ out, int E) {
    extern __shared__ char sm[];
    const uint32_t sbase = smem_u32(sm);
    const int tid = threadIdx.x;
    const int w = tid >> 5, lane = tid & 31;
    const int gid = lane >> 2, tig = lane & 3;
    const int rbase = (w & 3) * 32, cbase = (w >> 2) * 64;
    const int ebase = blockIdx.x * 128;

    int* sBatch = (int*)(sm + MISC_BASE);
    float* sB1 = (float*)(sm + MISC_BASE + 512);
    float* sB2 = (float*)(sm + MISC_BASE + 1024);
    float* sA2 = (float*)(sm + MISC_BASE + 1536);
    float* sC2 = (float*)(sm + MISC_BASE + 2048);

    if (tid < 128) {
        int e = ebase + tid;
        if (e >= E) e = E - 1;
        sBatch[tid] = batch[e];
        sB1[tid] = g_b1p[tid];
        sB2[tid] = g_b2p[tid];
        sA2[tid] = g_a2v[tid];
        sC2[tid] = g_c2v[tid];
    }

    // ---- precomputed ldsm lane offsets ----
    uint32_t aOff80[2], aOffAct[2], bOff80[4], bOffW[4];
#pragma unroll
    for (int mt = 0; mt < 2; mt++) {
        int r = rbase + mt * 16 + (lane & 15);
        aOff80[mt] = (uint32_t)r * 80 + (lane >> 4) * 16;
        aOffAct[mt] = (uint32_t)r * ACT_STRIDE + (lane >> 4) * 16;
    }
#pragma unroll
    for (int nt2 = 0; nt2 < 4; nt2++) {
        int n = cbase + nt2 * 16 + (lane & 7) + ((lane >> 4) & 1) * 8;
        bOff80[nt2] = (uint32_t)n * 80 + ((lane >> 3) & 1) * 16;
        bOffW[nt2] = (uint32_t)n * ACT_STRIDE + ((lane >> 3) & 1) * 16;
    }
    const int convR = tid & 127, convH = tid >> 7;

    // ---- PFA: stage layer-0 fp32 chunk x into STG[x&1] (own group) ----
    auto PFA = [&](int x) {
        if (x < 12) {
            const float* T = (x < 4) ? src : ((x < 8) ? dst_ : edg);
            const int coff = (x & 3) * 32;
            char* base = sm + (x & 1) * STG_BYTES;
#pragma unroll
            for (int i = 0; i < 4; i++) {
                int f = tid + i * 256;
                int row = f >> 3, u = f & 7;
                int e = ebase + row;
                if (e >= E) e = E - 1;
                cp16(base + row * STG_STRIDE + u * 16,
                     (const char*)(T + (size_t)e * 128 + coff) + u * 16);
            }
        }
        CPC;
    };
    // ---- PFB: layer-0 W0 chunk x into B[x%3] (own group) ----
    auto PFB = [&](int x) {
        if (x < 12) {
            char* base = sm + B_BASE + (x % 3) * BB_BYTES;
            const int kb = x * 32;
#pragma unroll
            for (int i = 0; i < 2; i++) {
                int f = tid + i * 256;
                int n = f >> 2, kh = f & 3;
                cp16(base + n * 80 + kh * 16,
                     (const char*)(g_W0h + (size_t)n * 384 + kb) + kh * 16);
            }
        }
        CPC;
    };
    // ---- CONV: staged fp32 chunk x -> fp16 A16[x&1] ----
    auto CONV = [&](int x) {
        const char* sp = sm + (x & 1) * STG_BYTES + convR * STG_STRIDE + convH * 64;
        float4 f0 = *(const float4*)(sp);
        float4 f1 = *(const float4*)(sp + 16);
        float4 f2 = *(const float4*)(sp + 32);
        float4 f3 = *(const float4*)(sp + 48);
        uint4 o0, o1;
        o0.x = h2u(__floats2half2_rn(f0.x, f0.y));
        o0.y = h2u(__floats2half2_rn(f0.z, f0.w));
        o0.z = h2u(__floats2half2_rn(f1.x, f1.y));
        o0.w = h2u(__floats2half2_rn(f1.z, f1.w));
        o1.x = h2u(__floats2half2_rn(f2.x, f2.y));
        o1.y = h2u(__floats2half2_rn(f2.z, f2.w));
        o1.z = h2u(__floats2half2_rn(f3.x, f3.y));
        o1.w = h2u(__floats2half2_rn(f3.z, f3.w));
        char* dp = sm + A16_BASE + (x & 1) * A16_BYTES + convR * 80 + convH * 32;
        *(uint4*)(dp) = o0;
        *(uint4*)(dp + 16) = o1;
    };
    // ---- load a 128x128 fp16 weight matrix into WBUF (stride 272), one group ----
    auto LOADW = [&](const __half* Wh) {
#pragma unroll
        for (int i = 0; i < 8; i++) {
            int f = tid + i * 256;           // 2048 16B-units
            int row = f >> 4, u = f & 15;
            cp16(sm + WBUF_BASE + row * ACT_STRIDE + u * 16,
                 (const char*)(Wh + (size_t)row * 128) + u * 16);
        }
        CPC;
    };

    float acc[2][8][4];
#pragma unroll
    for (int mt = 0; mt < 2; mt++)
#pragma unroll
        for (int nt = 0; nt < 8; nt++)
#pragma unroll
            for (int i = 0; i < 4; i++) acc[mt][nt][i] = 0.f;

    // ---- one k-step: interleaved ldsm/mma (first mma after 3 ldsm; b2/b3 hidden) ----
    auto MMAKS = [&](uint32_t aB, const uint32_t* aOff, uint32_t bB, const uint32_t* bOff,
                     int koff) {
        uint32_t a[2][4], b[4][4];
        ldsm4(a[0][0], a[0][1], a[0][2], a[0][3], aB + aOff[0] + koff);
        ldsm4(a[1][0], a[1][1], a[1][2], a[1][3], aB + aOff[1] + koff);
        ldsm4(b[0][0], b[0][1], b[0][2], b[0][3], bB + bOff[0] + koff);
        ldsm4(b[1][0], b[1][1], b[1][2], b[1][3], bB + bOff[1] + koff);
        // group 0 (b[0])
        mma16816(acc[0][0], a[0], b[0][0], b[0][1]);
        mma16816(acc[0][1], a[0], b[0][2], b[0][3]);
        mma16816(acc[1][0], a[1], b[0][0], b[0][1]);
        mma16816(acc[1][1], a[1], b[0][2], b[0][3]);
        ldsm4(b[2][0], b[2][1], b[2][2], b[2][3], bB + bOff[2] + koff);
        // group 1 (b[1])
        mma16816(acc[0][2], a[0], b[1][0], b[1][1]);
        mma16816(acc[0][3], a[0], b[1][2], b[1][3]);
        mma16816(acc[1][2], a[1], b[1][0], b[1][1]);
        mma16816(acc[1][3], a[1], b[1][2], b[1][3]);
        ldsm4(b[3][0], b[3][1], b[3][2], b[3][3], bB + bOff[3] + koff);
        // group 2 (b[2])
        mma16816(acc[0][4], a[0], b[2][0], b[2][1]);
        mma16816(acc[0][5], a[0], b[2][2], b[2][3]);
        mma16816(acc[1][4], a[1], b[2][0], b[2][1]);
        mma16816(acc[1][5], a[1], b[2][2], b[2][3]);
        // group 3 (b[3])
        mma16816(acc[0][6], a[0], b[3][0], b[3][1]);
        mma16816(acc[0][7], a[0], b[3][2], b[3][3]);
        mma16816(acc[1][6], a[1], b[3][0], b[3][1]);
        mma16816(acc[1][7], a[1], b[3][2], b[3][3]);
    };

    // ---- EPI body: acc -> add, relu, fp16 -> ACT; zero acc ----
    auto EPI = [&](bool first) {
#pragma unroll
        for (int mt = 0; mt < 2; mt++) {
#pragma unroll
            for (int nt = 0; nt < 8; nt++) {
                const int col = cbase + nt * 8 + 2 * tig;
#pragma unroll
                for (int rh = 0; rh < 2; rh++) {
                    const int row = rbase + mt * 16 + gid + rh * 8;
                    float ax, ay;
                    if (first) {
                        const float2 uv = *(const float2*)&g_U[(size_t)sBatch[row] * 128 + col];
                        ax = uv.x; ay = uv.y;
                    } else {
                        ax = sB1[col]; ay = sB1[col + 1];
                    }
                    float* c4 = acc[mt][nt];
                    float x = fmaxf(c4[rh * 2 + 0] + ax, 0.f);
                    float y = fmaxf(c4[rh * 2 + 1] + ay, 0.f);
                    *(__half2*)(sm + row * ACT_STRIDE + 2 * col) = __floats2half2_rn(x, y);
                    c4[rh * 2 + 0] = 0.f;
                    c4[rh * 2 + 1] = 0.f;
                }
            }
        }
    };

    // ---- layers 1/2: uninterrupted K=128 sweep (A=ACT at 0, B=WBUF resident) ----
    auto GEMM12 = [&]() {
#pragma unroll
        for (int ks = 0; ks < 8; ks++)
            MMAKS(sbase, aOffAct, sbase + WBUF_BASE, bOffW, ks * 32);
    };

    // ================= layer 0: 12 chunks — R12 pipeline, interleaved MMA =================
    __syncthreads();                 // misc tables visible
    PFA(0); PFB(0);                  // groups 0,1
    PFA(1); PFB(1);                  // groups 2,3
    CPW(2);                          // A(0), B(0) complete
    __syncthreads();                 // publish staged A(0)/B(0)
    CONV(0);                         // A16[0]; published by bar in iter 0

#pragma unroll 1
    for (int cg = 0; cg < 12; cg++) {
        // Outstanding at entry: B(cg), A(cg+1), B(cg+1). CPW(1) completes B(cg), A(cg+1).
        CPW(1);
        __syncthreads();             // publish cp.async data + last iter's CONV stores

        if (cg + 1 < 12) CONV(cg + 1);
        PFA(cg + 2);                 // empty group when cg+2 >= 12
        PFB(cg + 2);                 // empty group when cg+2 >= 12

        const uint32_t aB = sbase + A16_BASE + (cg & 1) * A16_BYTES;
        const uint32_t bB = sbase + B_BASE + (cg % 3) * BB_BYTES;
        MMAKS(aB, aOff80, bB, bOff80, 0);
        MMAKS(aB, aOff80, bB, bOff80, 32);
    }

    // ================= EPI0 (+ W1 load overlap) + GEMM1 =================
    __syncthreads();                 // MMA(11) reads done: STG, A16, B ring all dead
    LOADW(g_W1h);                    // W1 -> WBUF (aliases A16/B; safe post-bar)
    EPI(true);                       // writes ACT (aliases STG; dead)
    CPW(0);                          // W1 complete (+ leftover empty groups)
    __syncthreads();                 // publish ACT + W1

    GEMM12();                        // layer 1: K=128, W1 resident

    __syncthreads();                 // GEMM1 reads of ACT/WBUF done
    LOADW(g_W2h);                    // W2 -> WBUF
    EPI(false);                      // rewrite ACT
    CPW(0);
    __syncthreads();                 // publish ACT + W2

    GEMM12();                        // layer 2: K=128, W2 resident

    // ================= final epilogue: + b2', relu, BN2 affine, store =================
    const int Ev = E - ebase;
#pragma unroll
    for (int mt = 0; mt < 2; mt++) {
#pragma unroll
        for (int nt = 0; nt < 8; nt++) {
            const int col = cbase + nt * 8 + 2 * tig;
            const float bx = sB2[col], by = sB2[col + 1];
            const float axm = sA2[col], aym = sA2[col + 1];
            const float cxm = sC2[col], cym = sC2[col + 1];
#pragma unroll
            for (int rh = 0; rh < 2; rh++) {
                const int row = rbase + mt * 16 + gid + rh * 8;
                if (row < Ev) {
                    float* c4 = acc[mt][nt];
                    float2 v;
                    v.x = fmaxf(c4[rh * 2 + 0] + bx, 0.f) * axm + cxm;
                    v.y = fmaxf(c4[rh * 2 + 1] + by, 0.f) * aym + cym;
                    *(float2*)&out[(size_t)(ebase + row) * 128 + col] = v;
                }
            }
        }
    }
}

// ---------------- launch ----------------
extern "C" void kernel_launch(void* const* d_in, const int* in_sizes, int n_in,
                              void* d_out, int out_size) {
    const float* src  = (const float*)d_in[0];
    const float* dest = (const float*)d_in[1];
    const float* edge = (const float*)d_in[2];
    const float* u    = (const float*)d_in[3];
    const int*   batch = (const int*)d_in[4];
    const float* W0 = (const float*)d_in[5];
    const float* b0 = (const float*)d_in[6];
    const float* W1 = (const float*)d_in[7];
    const float* b1 = (const float*)d_in[8];
    const float* W2 = (const float*)d_in[9];
    const float* b2 = (const float*)d_in[10];
    const float* g0 = (const float*)d_in[11];
    const float* be0 = (const float*)d_in[12];
    const float* m0 = (const float*)d_in[13];
    const float* v0 = (const float*)d_in[14];
    const float* g1 = (const float*)d_in[15];
    const float* be1 = (const float*)d_in[16];
    const float* m1 = (const float*)d_in[17];
    const float* v1 = (const float*)d_in[18];
    const float* g2 = (const float*)d_in[19];
    const float* be2 = (const float*)d_in[20];
    const float* m2 = (const float*)d_in[21];
    const float* v2 = (const float*)d_in[22];

    int E = in_sizes[0] / 128;

    cudaFuncSetAttribute(megnet_main, cudaFuncAttributeMaxDynamicSharedMemorySize, SMEM_BYTES);

    prep_weights<<<320, 256>>>(W0, W1, W2, g0, v0, g1, v1);
    prep_bias<<<128, 128>>>(W1, b1, W2, b2, g0, be0, m0, v0, g1, be1, m1, v1,
                            g2, be2, m2, v2);
    prep_U<<<64, 128>>>(u, W0, b0);
    megnet_main<<<(E + 127) / 128, 256, SMEM_BYTES>>>(src, dest, edge, batch, (float*)d_out, E);
}

// round 16
// speedup vs baseline: 1.0043x; 1.0043x over previous
#include <cuda_runtime.h>
#include <cuda_fp16.h>
#include <cstdint>

// ---------------- smem layout (bytes) ----------------
#define STG_STRIDE 144                      // fp32 staging row: 128B data + 16B pad (16B-mult!)
#define STG_BYTES  (128 * 144)              // 18432; 2 buffers at 0
// post-layer0: ACT (128 x 272 = 34816) aliases the STG region [0, 36864)
#define ACT_STRIDE 272
#define A16_BASE   (2 * STG_BYTES)          // 36864: layer-0 fp16 A chunks, 2 bufs
#define A16_BYTES  (128 * 80)               // 10240
#define B_BASE     (A16_BASE + 2 * A16_BYTES)   // 57344: layer-0 B ring, 3 stages
#define BB_BYTES   (128 * 80)               // 10240
// post-layer0: WBUF (34816) aliases [A16_BASE, A16_BASE+34816)
#define WBUF_BASE  A16_BASE
#define MISC_BASE  (B_BASE + 3 * BB_BYTES)  // 88064
#define SMEM_BYTES (MISC_BASE + 2560)       // 90624  (2 CTAs/SM)

// ---------------- device scratch ----------------
__device__ __half g_W0h[128 * 384];  // [n][k] fp16 W0^T (k = 0..383)
__device__ __half g_W1h[128 * 128];  // [n][k] fp16( a0[k] * W1[k][n] )
__device__ __half g_W2h[128 * 128];  // [n][k] fp16( a1[k] * W2[k][n] )
__device__ float  g_U[64 * 128];     // U'[b][n] = b0[n] + u[b]@W0[384:,n]
__device__ float  g_b1p[128];
__device__ float  g_b2p[128];
__device__ float  g_a2v[128];
__device__ float  g_c2v[128];

// ---------------- helpers ----------------
__device__ __forceinline__ uint32_t smem_u32(const void* p) {
    uint32_t a;
    asm("{ .reg .u64 t; cvta.to.shared.u64 t, %1; cvt.u32.u64 %0, t; }" : "=r"(a) : "l"(p));
    return a;
}
__device__ __forceinline__ void cp16(void* dst, const void* src) {
    uint32_t sa = smem_u32(dst);
    asm volatile("cp.async.cg.shared.global [%0], [%1], 16;" :: "r"(sa), "l"(src) : "memory");
}
#define CPC asm volatile("cp.async.commit_group;" ::: "memory")
#define CPW(n) asm volatile("cp.async.wait_group %0;" :: "n"(n) : "memory")

__device__ __forceinline__ void ldsm4(uint32_t& r0, uint32_t& r1, uint32_t& r2, uint32_t& r3,
                                      uint32_t addr) {
    asm volatile("ldmatrix.sync.aligned.m8n8.x4.shared.b16 {%0,%1,%2,%3}, [%4];"
                 : "=r"(r0), "=r"(r1), "=r"(r2), "=r"(r3) : "r"(addr));
}
__device__ __forceinline__ void mma16816(float* c, const uint32_t* a, uint32_t b0, uint32_t b1) {
    asm volatile(
        "mma.sync.aligned.m16n8k16.row.col.f32.f16.f16.f32 "
        "{%0,%1,%2,%3}, {%4,%5,%6,%7}, {%8,%9}, {%0,%1,%2,%3};"
        : "+f"(c[0]), "+f"(c[1]), "+f"(c[2]), "+f"(c[3])
        : "r"(a[0]), "r"(a[1]), "r"(a[2]), "r"(a[3]), "r"(b0), "r"(b1));
}
__device__ __forceinline__ uint32_t h2u(__half2 h) {
    union { __half2 h; uint32_t u; } cv;
    cv.h = h;
    return cv.u;
}

// ---------------- merged prep kernel ----------------
// blocks 0..319   : weight conversion (81920 elements, 256 thr)
// blocks 320..447 : per-column bias folding (n = blk-320, 128 thr)
// blocks 448..511 : U' precompute (b = blk-448, 128 thr)
__global__ void prep_all(const float* __restrict__ W0, const float* __restrict__ b0,
                         const float* __restrict__ W1, const float* __restrict__ b1,
                         const float* __restrict__ W2, const float* __restrict__ b2,
                         const float* __restrict__ u,
                         const float* __restrict__ g0, const float* __restrict__ be0,
                         const float* __restrict__ m0, const float* __restrict__ v0,
                         const float* __restrict__ g1, const float* __restrict__ be1,
                         const float* __restrict__ m1, const float* __restrict__ v1,
                         const float* __restrict__ g2, const float* __restrict__ be2,
                         const float* __restrict__ m2, const float* __restrict__ v2) {
    const int blk = blockIdx.x;
    if (blk < 320) {
        int i = blk * 256 + threadIdx.x;
        if (i < 49152) {                         // W0h [n][k]
            int n = i / 384, k = i - n * 384;
            g_W0h[i] = __float2half(W0[k * 128 + n]);
        } else if (i < 65536) {                  // W1h [n][k] scaled by a0[k]
            int j = i - 49152;
            int n = j >> 7, k = j & 127;
            float a0 = g0[k] * rsqrtf(v0[k] + 1e-5f);
            g_W1h[j] = __float2half(a0 * W1[k * 128 + n]);
        } else if (i < 81920) {                  // W2h [n][k] scaled by a1[k]
            int j = i - 65536;
            int n = j >> 7, k = j & 127;
            float a1 = g1[k] * rsqrtf(v1[k] + 1e-5f);
            g_W2h[j] = __float2half(a1 * W2[k * 128 + n]);
        }
    } else if (blk < 448) {
        __shared__ float r1[128], r2[128];
        const int n = blk - 320, k = threadIdx.x;
        if (k < 128) {
            float a0 = g0[k] * rsqrtf(v0[k] + 1e-5f);
            float c0 = be0[k] - m0[k] * a0;
            float a1 = g1[k] * rsqrtf(v1[k] + 1e-5f);
            float c1 = be1[k] - m1[k] * a1;
            r1[k] = c0 * W1[k * 128 + n];
            r2[k] = c1 * W2[k * 128 + n];
        }
        __syncthreads();
        for (int off = 64; off; off >>= 1) {
            if (k < off) { r1[k] += r1[k + off]; r2[k] += r2[k + off]; }
            __syncthreads();
        }
        if (k == 0) {
            g_b1p[n] = b1[n] + r1[0];
            g_b2p[n] = b2[n] + r2[0];
            float a2 = g2[n] * rsqrtf(v2[n] + 1e-5f);
            g_a2v[n] = a2;
            g_c2v[n] = be2[n] - m2[n] * a2;
        }
    } else {
        __shared__ float ub[128];
        const int b = blk - 448, n = threadIdx.x;
        if (n < 128) {
            ub[n] = u[b * 128 + n];
        }
        __syncthreads();
        if (n < 128) {
            float acc = b0[n];
            for (int k = 0; k < 128; k++) acc += ub[k] * W0[(384 + k) * 128 + n];
            g_U[b * 128 + n] = acc;
        }
    }
}

// ---------------- main kernel ----------------
__global__ void __launch_bounds__(256, 2)
megnet_main(const float* __restrict__ src, const float* __restrict__ dst_,
            const float* __restrict__ edg, const int* __restrict__ batch,
            float* __restrict__ out, int E) {
    extern __shared__ char sm[];
    const uint32_t sbase = smem_u32(sm);
    const int tid = threadIdx.x;
    const int w = tid >> 5, lane = tid & 31;
    const int gid = lane >> 2, tig = lane & 3;
    const int rbase = (w & 3) * 32, cbase = (w >> 2) * 64;
    const int ebase = blockIdx.x * 128;

    int* sBatch = (int*)(sm + MISC_BASE);
    float* sB1 = (float*)(sm + MISC_BASE + 512);
    float* sB2 = (float*)(sm + MISC_BASE + 1024);
    float* sA2 = (float*)(sm + MISC_BASE + 1536);
    float* sC2 = (float*)(sm + MISC_BASE + 2048);

    // ---- precomputed ldsm lane offsets ----
    uint32_t aOff80[2], aOffAct[2], bOff80[4], bOffW[4];
#pragma unroll
    for (int mt = 0; mt < 2; mt++) {
        int r = rbase + mt * 16 + (lane & 15);
        aOff80[mt] = (uint32_t)r * 80 + (lane >> 4) * 16;
        aOffAct[mt] = (uint32_t)r * ACT_STRIDE + (lane >> 4) * 16;
    }
#pragma unroll
    for (int nt2 = 0; nt2 < 4; nt2++) {
        int n = cbase + nt2 * 16 + (lane & 7) + ((lane >> 4) & 1) * 8;
        bOff80[nt2] = (uint32_t)n * 80 + ((lane >> 3) & 1) * 16;
        bOffW[nt2] = (uint32_t)n * ACT_STRIDE + ((lane >> 3) & 1) * 16;
    }
    const int convR = tid & 127, convH = tid >> 7;

    // ---- PFA: stage layer-0 fp32 chunk x into STG[x&1] (own group) ----
    auto PFA = [&](int x) {
        if (x < 12) {
            const float* T = (x < 4) ? src : ((x < 8) ? dst_ : edg);
            const int coff = (x & 3) * 32;
            char* base = sm + (x & 1) * STG_BYTES;
#pragma unroll
            for (int i = 0; i < 4; i++) {
                int f = tid + i * 256;
                int row = f >> 3, u = f & 7;
                int e = ebase + row;
                if (e >= E) e = E - 1;
                cp16(base + row * STG_STRIDE + u * 16,
                     (const char*)(T + (size_t)e * 128 + coff) + u * 16);
            }
        }
        CPC;
    };
    // ---- PFB: layer-0 W0 chunk x into B[x%3] (own group) ----
    auto PFB = [&](int x) {
        if (x < 12) {
            char* base = sm + B_BASE + (x % 3) * BB_BYTES;
            const int kb = x * 32;
#pragma unroll
            for (int i = 0; i < 2; i++) {
                int f = tid + i * 256;
                int n = f >> 2, kh = f & 3;
                cp16(base + n * 80 + kh * 16,
                     (const char*)(g_W0h + (size_t)n * 384 + kb) + kh * 16);
            }
        }
        CPC;
    };
    // ---- CONV: staged fp32 chunk x -> fp16 A16[x&1] ----
    auto CONV = [&](int x) {
        const char* sp = sm + (x & 1) * STG_BYTES + convR * STG_STRIDE + convH * 64;
        float4 f0 = *(const float4*)(sp);
        float4 f1 = *(const float4*)(sp + 16);
        float4 f2 = *(const float4*)(sp + 32);
        float4 f3 = *(const float4*)(sp + 48);
        uint4 o0, o1;
        o0.x = h2u(__floats2half2_rn(f0.x, f0.y));
        o0.y = h2u(__floats2half2_rn(f0.z, f0.w));
        o0.z = h2u(__floats2half2_rn(f1.x, f1.y));
        o0.w = h2u(__floats2half2_rn(f1.z, f1.w));
        o1.x = h2u(__floats2half2_rn(f2.x, f2.y));
        o1.y = h2u(__floats2half2_rn(f2.z, f2.w));
        o1.z = h2u(__floats2half2_rn(f3.x, f3.y));
        o1.w = h2u(__floats2half2_rn(f3.z, f3.w));
        char* dp = sm + A16_BASE + (x & 1) * A16_BYTES + convR * 80 + convH * 32;
        *(uint4*)(dp) = o0;
        *(uint4*)(dp + 16) = o1;
    };
    // ---- load a 128x128 fp16 weight matrix into WBUF (stride 272), one group ----
    auto LOADW = [&](const __half* Wh) {
#pragma unroll
        for (int i = 0; i < 8; i++) {
            int f = tid + i * 256;           // 2048 16B-units
            int row = f >> 4, u = f & 15;
            cp16(sm + WBUF_BASE + row * ACT_STRIDE + u * 16,
                 (const char*)(Wh + (size_t)row * 128) + u * 16);
        }
        CPC;
    };

    float acc[2][8][4];
#pragma unroll
    for (int mt = 0; mt < 2; mt++)
#pragma unroll
        for (int nt = 0; nt < 8; nt++)
#pragma unroll
            for (int i = 0; i < 4; i++) acc[mt][nt][i] = 0.f;

    // ---- EPI body: acc -> add, relu, fp16 -> ACT; zero acc ----
    auto EPI = [&](bool first) {
#pragma unroll
        for (int mt = 0; mt < 2; mt++) {
#pragma unroll
            for (int nt = 0; nt < 8; nt++) {
                const int col = cbase + nt * 8 + 2 * tig;
#pragma unroll
                for (int rh = 0; rh < 2; rh++) {
                    const int row = rbase + mt * 16 + gid + rh * 8;
                    float ax, ay;
                    if (first) {
                        const float2 uv = *(const float2*)&g_U[(size_t)sBatch[row] * 128 + col];
                        ax = uv.x; ay = uv.y;
                    } else {
                        ax = sB1[col]; ay = sB1[col + 1];
                    }
                    float* c4 = acc[mt][nt];
                    float x = fmaxf(c4[rh * 2 + 0] + ax, 0.f);
                    float y = fmaxf(c4[rh * 2 + 1] + ay, 0.f);
                    *(__half2*)(sm + row * ACT_STRIDE + 2 * col) = __floats2half2_rn(x, y);
                    c4[rh * 2 + 0] = 0.f;
                    c4[rh * 2 + 1] = 0.f;
                }
            }
        }
    };

    // ---- layers 1/2: uninterrupted K=128 sweep (A=ACT at 0, B=WBUF resident) ----
    auto GEMM12 = [&]() {
        const uint32_t aB = sbase;
        const uint32_t bB = sbase + WBUF_BASE;
#pragma unroll
        for (int ks = 0; ks < 8; ks++) {
            uint32_t a[2][4], b[4][4];
#pragma unroll
            for (int mt = 0; mt < 2; mt++)
                ldsm4(a[mt][0], a[mt][1], a[mt][2], a[mt][3], aB + aOffAct[mt] + ks * 32);
#pragma unroll
            for (int nt2 = 0; nt2 < 4; nt2++)
                ldsm4(b[nt2][0], b[nt2][1], b[nt2][2], b[nt2][3], bB + bOffW[nt2] + ks * 32);
#pragma unroll
            for (int mt = 0; mt < 2; mt++)
#pragma unroll
                for (int nt2 = 0; nt2 < 4; nt2++) {
                    mma16816(acc[mt][nt2 * 2 + 0], a[mt], b[nt2][0], b[nt2][1]);
                    mma16816(acc[mt][nt2 * 2 + 1], a[mt], b[nt2][2], b[nt2][3]);
                }
        }
    };

    // ================= layer 0: 12 chunks — R12 pipeline verbatim =================
    PFA(0); PFB(0);                  // groups 0,1
    PFA(1); PFB(1);                  // groups 2,3
    CPW(2);                          // A(0), B(0) complete
    __syncthreads();                 // publish staged A(0)/B(0)
    CONV(0);                         // A16[0]; published by bar in iter 0

#pragma unroll 1
    for (int cg = 0; cg < 12; cg++) {
        // Outstanding at entry: B(cg), A(cg+1), B(cg+1). CPW(1) completes B(cg), A(cg+1).
        CPW(1);
        __syncthreads();             // publish cp.async data + last iter's CONV stores

        if (cg + 1 < 12) CONV(cg + 1);
        PFA(cg + 2);                 // empty group when cg+2 >= 12
        PFB(cg + 2);                 // empty group when cg+2 >= 12

        const uint32_t aB = sbase + A16_BASE + (cg & 1) * A16_BYTES;
        const uint32_t bB = sbase + B_BASE + (cg % 3) * BB_BYTES;
#pragma unroll
        for (int ks = 0; ks < 2; ks++) {
            uint32_t a[2][4], b[4][4];
#pragma unroll
            for (int mt = 0; mt < 2; mt++)
                ldsm4(a[mt][0], a[mt][1], a[mt][2], a[mt][3], aB + aOff80[mt] + ks * 32);
#pragma unroll
            for (int nt2 = 0; nt2 < 4; nt2++)
                ldsm4(b[nt2][0], b[nt2][1], b[nt2][2], b[nt2][3], bB + bOff80[nt2] + ks * 32);
#pragma unroll
            for (int mt = 0; mt < 2; mt++)
#pragma unroll
                for (int nt2 = 0; nt2 < 4; nt2++) {
                    mma16816(acc[mt][nt2 * 2 + 0], a[mt], b[nt2][0], b[nt2][1]);
                    mma16816(acc[mt][nt2 * 2 + 1], a[mt], b[nt2][2], b[nt2][3]);
                }
        }
    }

    // ---- misc tables: first consumed after the next barrier (EPI0 / final epi) ----
    if (tid < 128) {
        int e = ebase + tid;
        if (e >= E) e = E - 1;
        sBatch[tid] = batch[e];
        sB1[tid] = g_b1p[tid];
        sB2[tid] = g_b2p[tid];
        sA2[tid] = g_a2v[tid];
        sC2[tid] = g_c2v[tid];
    }

    // ================= EPI0 (+ W1 load overlap) + GEMM1 =================
    __syncthreads();                 // MMA(11) reads done; misc tables published
    LOADW(g_W1h);                    // W1 -> WBUF (aliases A16/B; safe post-bar)
    EPI(true);                       // writes ACT (aliases STG; dead)
    CPW(0);                          // W1 complete (+ leftover empty groups)
    __syncthreads();                 // publish ACT + W1

    GEMM12();                        // layer 1: K=128, W1 resident

    __syncthreads();                 // GEMM1 reads of ACT/WBUF done
    LOADW(g_W2h);                    // W2 -> WBUF
    EPI(false);                      // rewrite ACT
    CPW(0);
    __syncthreads();                 // publish ACT + W2

    GEMM12();                        // layer 2: K=128, W2 resident

    // ================= final epilogue: + b2', relu, BN2 affine, store =================
    const int Ev = E - ebase;
#pragma unroll
    for (int mt = 0; mt < 2; mt++) {
#pragma unroll
        for (int nt = 0; nt < 8; nt++) {
            const int col = cbase + nt * 8 + 2 * tig;
            const float bx = sB2[col], by = sB2[col + 1];
            const float axm = sA2[col], aym = sA2[col + 1];
            const float cxm = sC2[col], cym = sC2[col + 1];
#pragma unroll
            for (int rh = 0; rh < 2; rh++) {
                const int row = rbase + mt * 16 + gid + rh * 8;
                if (row < Ev) {
                    float* c4 = acc[mt][nt];
                    float2 v;
                    v.x = fmaxf(c4[rh * 2 + 0] + bx, 0.f) * axm + cxm;
                    v.y = fmaxf(c4[rh * 2 + 1] + by, 0.f) * aym + cym;
                    *(float2*)&out[(size_t)(ebase + row) * 128 + col] = v;
                }
            }
        }
    }
}

// ---------------- launch ----------------
extern "C" void kernel_launch(void* const* d_in, const int* in_sizes, int n_in,
                              void* d_out, int out_size) {
    const float* src  = (const float*)d_in[0];
    const float* dest = (const float*)d_in[1];
    const float* edge = (const float*)d_in[2];
    const float* u    = (const float*)d_in[3];
    const int*   batch = (const int*)d_in[4];
    const float* W0 = (const float*)d_in[5];
    const float* b0 = (const float*)d_in[6];
    const float* W1 = (const float*)d_in[7];
    const float* b1 = (const float*)d_in[8];
    const float* W2 = (const float*)d_in[9];
    const float* b2 = (const float*)d_in[10];
    const float* g0 = (const float*)d_in[11];
    const float* be0 = (const float*)d_in[12];
    const float* m0 = (const float*)d_in[13];
    const float* v0 = (const float*)d_in[14];
    const float* g1 = (const float*)d_in[15];
    const float* be1 = (const float*)d_in[16];
    const float* m1 = (const float*)d_in[17];
    const float* v1 = (const float*)d_in[18];
    const float* g2 = (const float*)d_in[19];
    const float* be2 = (const float*)d_in[20];
    const float* m2 = (const float*)d_in[21];
    const float* v2 = (const float*)d_in[22];

    int E = in_sizes[0] / 128;

    cudaFuncSetAttribute(megnet_main, cudaFuncAttributeMaxDynamicSharedMemorySize, SMEM_BYTES);

    prep_all<<<512, 256>>>(W0, b0, W1, b1, W2, b2, u,
                           g0, be0, m0, v0, g1, be1, m1, v1, g2, be2, m2, v2);
    megnet_main<<<(E + 127) / 128, 256, SMEM_BYTES>>>(src, dest, edge, batch, (float*)d_out, E);
}

// round 17
// speedup vs baseline: 1.0133x; 1.0089x over previous
#include <cuda_runtime.h>
#include <cuda_fp16.h>
#include <cstdint>

// ---------------- smem layout (bytes) ----------------
#define STG_STRIDE 144                      // fp32 staging row: 128B data + 16B pad (16B-mult!)
#define STG_BYTES  (128 * 144)              // 18432; 2 buffers at 0
// post-layer0: ACT (128 x 272 = 34816) aliases the STG region [0, 36864)
#define ACT_STRIDE 272
#define A16_BASE   (2 * STG_BYTES)          // 36864: layer-0 fp16 A chunks, 2 bufs
#define A16_BYTES  (128 * 80)               // 10240
#define B_BASE     (A16_BASE + 2 * A16_BYTES)   // 57344: layer-0 B ring, 3 stages
#define BB_BYTES   (128 * 80)               // 10240
// post-layer0: WBUF (34816) aliases [A16_BASE, A16_BASE+34816)
#define WBUF_BASE  A16_BASE
#define MISC_BASE  (B_BASE + 3 * BB_BYTES)  // 88064
#define SMEM_BYTES (MISC_BASE + 2560)       // 90624  (2 CTAs/SM)

// ---------------- device scratch ----------------
__device__ __half g_W0h[128 * 384];  // [n][k] fp16 W0^T (k = 0..383)
__device__ __half g_W1h[128 * 128];  // [n][k] fp16( a0[k] * W1[k][n] )
__device__ __half g_W2h[128 * 128];  // [n][k] fp16( a1[k] * W2[k][n] )
__device__ float  g_U[64 * 128];     // U'[b][n] = b0[n] + u[b]@W0[384:,n]
__device__ float  g_b1p[128];
__device__ float  g_b2p[128];
__device__ float  g_a2v[128];
__device__ float  g_c2v[128];

// ---------------- helpers ----------------
__device__ __forceinline__ uint32_t smem_u32(const void* p) {
    uint32_t a;
    asm("{ .reg .u64 t; cvta.to.shared.u64 t, %1; cvt.u32.u64 %0, t; }" : "=r"(a) : "l"(p));
    return a;
}
__device__ __forceinline__ void cp16(void* dst, const void* src) {
    uint32_t sa = smem_u32(dst);
    asm volatile("cp.async.cg.shared.global [%0], [%1], 16;" :: "r"(sa), "l"(src) : "memory");
}
#define CPC asm volatile("cp.async.commit_group;" ::: "memory")
#define CPW(n) asm volatile("cp.async.wait_group %0;" :: "n"(n) : "memory")

__device__ __forceinline__ void ldsm4(uint32_t& r0, uint32_t& r1, uint32_t& r2, uint32_t& r3,
                                      uint32_t addr) {
    asm volatile("ldmatrix.sync.aligned.m8n8.x4.shared.b16 {%0,%1,%2,%3}, [%4];"
                 : "=r"(r0), "=r"(r1), "=r"(r2), "=r"(r3) : "r"(addr));
}
__device__ __forceinline__ void mma16816(float* c, const uint32_t* a, uint32_t b0, uint32_t b1) {
    asm volatile(
        "mma.sync.aligned.m16n8k16.row.col.f32.f16.f16.f32 "
        "{%0,%1,%2,%3}, {%4,%5,%6,%7}, {%8,%9}, {%0,%1,%2,%3};"
        : "+f"(c[0]), "+f"(c[1]), "+f"(c[2]), "+f"(c[3])
        : "r"(a[0]), "r"(a[1]), "r"(a[2]), "r"(a[3]), "r"(b0), "r"(b1));
}
__device__ __forceinline__ uint32_t h2u(__half2 h) {
    union { __half2 h; uint32_t u; } cv;
    cv.h = h;
    return cv.u;
}

// ---------------- merged prep kernel ----------------
// blocks 0..319   : weight conversion (81920 elements, 256 thr)
// blocks 320..447 : per-column bias folding (n = blk-320, 128 thr)
// blocks 448..511 : U' precompute (b = blk-448, 128 thr)
__global__ void prep_all(const float* __restrict__ W0, const float* __restrict__ b0,
                         const float* __restrict__ W1, const float* __restrict__ b1,
                         const float* __restrict__ W2, const float* __restrict__ b2,
                         const float* __restrict__ u,
                         const float* __restrict__ g0, const float* __restrict__ be0,
                         const float* __restrict__ m0, const float* __restrict__ v0,
                         const float* __restrict__ g1, const float* __restrict__ be1,
                         const float* __restrict__ m1, const float* __restrict__ v1,
                         const float* __restrict__ g2, const float* __restrict__ be2,
                         const float* __restrict__ m2, const float* __restrict__ v2) {
    const int blk = blockIdx.x;
    if (blk < 320) {
        int i = blk * 256 + threadIdx.x;
        if (i < 49152) {                         // W0h [n][k]
            int n = i / 384, k = i - n * 384;
            g_W0h[i] = __float2half(W0[k * 128 + n]);
        } else if (i < 65536) {                  // W1h [n][k] scaled by a0[k]
            int j = i - 49152;
            int n = j >> 7, k = j & 127;
            float a0 = g0[k] * rsqrtf(v0[k] + 1e-5f);
            g_W1h[j] = __float2half(a0 * W1[k * 128 + n]);
        } else if (i < 81920) {                  // W2h [n][k] scaled by a1[k]
            int j = i - 65536;
            int n = j >> 7, k = j & 127;
            float a1 = g1[k] * rsqrtf(v1[k] + 1e-5f);
            g_W2h[j] = __float2half(a1 * W2[k * 128 + n]);
        }
    } else if (blk < 448) {
        __shared__ float r1[128], r2[128];
        const int n = blk - 320, k = threadIdx.x;
        if (k < 128) {
            float a0 = g0[k] * rsqrtf(v0[k] + 1e-5f);
            float c0 = be0[k] - m0[k] * a0;
            float a1 = g1[k] * rsqrtf(v1[k] + 1e-5f);
            float c1 = be1[k] - m1[k] * a1;
            r1[k] = c0 * W1[k * 128 + n];
            r2[k] = c1 * W2[k * 128 + n];
        }
        __syncthreads();
        for (int off = 64; off; off >>= 1) {
            if (k < off) { r1[k] += r1[k + off]; r2[k] += r2[k + off]; }
            __syncthreads();
        }
        if (k == 0) {
            g_b1p[n] = b1[n] + r1[0];
            g_b2p[n] = b2[n] + r2[0];
            float a2 = g2[n] * rsqrtf(v2[n] + 1e-5f);
            g_a2v[n] = a2;
            g_c2v[n] = be2[n] - m2[n] * a2;
        }
    } else {
        __shared__ float ub[128];
        const int b = blk - 448, n = threadIdx.x;
        if (n < 128) {
            ub[n] = u[b * 128 + n];
        }
        __syncthreads();
        if (n < 128) {
            float acc = b0[n];
            for (int k = 0; k < 128; k++) acc += ub[k] * W0[(384 + k) * 128 + n];
            g_U[b * 128 + n] = acc;
        }
    }
}

// ---------------- main kernel ----------------
__global__ void __launch_bounds__(256, 2)
megnet_main(const float* __restrict__ src, const float* __restrict__ dst_,
            const float* __restrict__ edg, const int* __restrict__ batch,
            float* __restrict__ out, int E) {
    extern __shared__ char sm[];
    const uint32_t sbase = smem_u32(sm);
    const int tid = threadIdx.x;
    const int w = tid >> 5, lane = tid & 31;
    const int gid = lane >> 2, tig = lane & 3;
    const int rbase = (w & 3) * 32, cbase = (w >> 2) * 64;
    const int ebase = blockIdx.x * 128;

    // ---- cross-CTA phase stagger: co-resident CTAs are bid and bid+148 (2/SM).
    // Delay the odd SM-slot by ~half a chunk period so the two CTAs' LSU/tensor
    // phases interleave instead of colliding. Output-invariant.
    if ((blockIdx.x / 148) & 1) __nanosleep(700);

    int* sBatch = (int*)(sm + MISC_BASE);
    float* sB1 = (float*)(sm + MISC_BASE + 512);
    float* sB2 = (float*)(sm + MISC_BASE + 1024);
    float* sA2 = (float*)(sm + MISC_BASE + 1536);
    float* sC2 = (float*)(sm + MISC_BASE + 2048);

    if (tid < 128) {
        int e = ebase + tid;
        if (e >= E) e = E - 1;
        sBatch[tid] = batch[e];
        sB1[tid] = g_b1p[tid];
        sB2[tid] = g_b2p[tid];
        sA2[tid] = g_a2v[tid];
        sC2[tid] = g_c2v[tid];
    }

    // ---- precomputed ldsm lane offsets ----
    uint32_t aOff80[2], aOffAct[2], bOff80[4], bOffW[4];
#pragma unroll
    for (int mt = 0; mt < 2; mt++) {
        int r = rbase + mt * 16 + (lane & 15);
        aOff80[mt] = (uint32_t)r * 80 + (lane >> 4) * 16;
        aOffAct[mt] = (uint32_t)r * ACT_STRIDE + (lane >> 4) * 16;
    }
#pragma unroll
    for (int nt2 = 0; nt2 < 4; nt2++) {
        int n = cbase + nt2 * 16 + (lane & 7) + ((lane >> 4) & 1) * 8;
        bOff80[nt2] = (uint32_t)n * 80 + ((lane >> 3) & 1) * 16;
        bOffW[nt2] = (uint32_t)n * ACT_STRIDE + ((lane >> 3) & 1) * 16;
    }
    const int convR = tid & 127, convH = tid >> 7;

    // ---- PFA: stage layer-0 fp32 chunk x into STG[x&1] (own group) ----
    auto PFA = [&](int x) {
        if (x < 12) {
            const float* T = (x < 4) ? src : ((x < 8) ? dst_ : edg);
            const int coff = (x & 3) * 32;
            char* base = sm + (x & 1) * STG_BYTES;
#pragma unroll
            for (int i = 0; i < 4; i++) {
                int f = tid + i * 256;
                int row = f >> 3, u = f & 7;
                int e = ebase + row;
                if (e >= E) e = E - 1;
                cp16(base + row * STG_STRIDE + u * 16,
                     (const char*)(T + (size_t)e * 128 + coff) + u * 16);
            }
        }
        CPC;
    };
    // ---- PFB: layer-0 W0 chunk x into B[x%3] (own group) ----
    auto PFB = [&](int x) {
        if (x < 12) {
            char* base = sm + B_BASE + (x % 3) * BB_BYTES;
            const int kb = x * 32;
#pragma unroll
            for (int i = 0; i < 2; i++) {
                int f = tid + i * 256;
                int n = f >> 2, kh = f & 3;
                cp16(base + n * 80 + kh * 16,
                     (const char*)(g_W0h + (size_t)n * 384 + kb) + kh * 16);
            }
        }
        CPC;
    };
    // ---- CONV: staged fp32 chunk x -> fp16 A16[x&1] ----
    auto CONV = [&](int x) {
        const char* sp = sm + (x & 1) * STG_BYTES + convR * STG_STRIDE + convH * 64;
        float4 f0 = *(const float4*)(sp);
        float4 f1 = *(const float4*)(sp + 16);
        float4 f2 = *(const float4*)(sp + 32);
        float4 f3 = *(const float4*)(sp + 48);
        uint4 o0, o1;
        o0.x = h2u(__floats2half2_rn(f0.x, f0.y));
        o0.y = h2u(__floats2half2_rn(f0.z, f0.w));
        o0.z = h2u(__floats2half2_rn(f1.x, f1.y));
        o0.w = h2u(__floats2half2_rn(f1.z, f1.w));
        o1.x = h2u(__floats2half2_rn(f2.x, f2.y));
        o1.y = h2u(__floats2half2_rn(f2.z, f2.w));
        o1.z = h2u(__floats2half2_rn(f3.x, f3.y));
        o1.w = h2u(__floats2half2_rn(f3.z, f3.w));
        char* dp = sm + A16_BASE + (x & 1) * A16_BYTES + convR * 80 + convH * 32;
        *(uint4*)(dp) = o0;
        *(uint4*)(dp + 16) = o1;
    };
    // ---- load a 128x128 fp16 weight matrix into WBUF (stride 272), one group ----
    auto LOADW = [&](const __half* Wh) {
#pragma unroll
        for (int i = 0; i < 8; i++) {
            int f = tid + i * 256;           // 2048 16B-units
            int row = f >> 4, u = f & 15;
            cp16(sm + WBUF_BASE + row * ACT_STRIDE + u * 16,
                 (const char*)(Wh + (size_t)row * 128) + u * 16);
        }
        CPC;
    };

    float acc[2][8][4];
#pragma unroll
    for (int mt = 0; mt < 2; mt++)
#pragma unroll
        for (int nt = 0; nt < 8; nt++)
#pragma unroll
            for (int i = 0; i < 4; i++) acc[mt][nt][i] = 0.f;

    // ---- EPI body: acc -> add, relu, fp16 -> ACT; zero acc ----
    auto EPI = [&](bool first) {
#pragma unroll
        for (int mt = 0; mt < 2; mt++) {
#pragma unroll
            for (int nt = 0; nt < 8; nt++) {
                const int col = cbase + nt * 8 + 2 * tig;
#pragma unroll
                for (int rh = 0; rh < 2; rh++) {
                    const int row = rbase + mt * 16 + gid + rh * 8;
                    float ax, ay;
                    if (first) {
                        const float2 uv = *(const float2*)&g_U[(size_t)sBatch[row] * 128 + col];
                        ax = uv.x; ay = uv.y;
                    } else {
                        ax = sB1[col]; ay = sB1[col + 1];
                    }
                    float* c4 = acc[mt][nt];
                    float x = fmaxf(c4[rh * 2 + 0] + ax, 0.f);
                    float y = fmaxf(c4[rh * 2 + 1] + ay, 0.f);
                    *(__half2*)(sm + row * ACT_STRIDE + 2 * col) = __floats2half2_rn(x, y);
                    c4[rh * 2 + 0] = 0.f;
                    c4[rh * 2 + 1] = 0.f;
                }
            }
        }
    };

    // ---- layers 1/2: uninterrupted K=128 sweep (A=ACT at 0, B=WBUF resident) ----
    auto GEMM12 = [&]() {
        const uint32_t aB = sbase;
        const uint32_t bB = sbase + WBUF_BASE;
#pragma unroll
        for (int ks = 0; ks < 8; ks++) {
            uint32_t a[2][4], b[4][4];
#pragma unroll
            for (int mt = 0; mt < 2; mt++)
                ldsm4(a[mt][0], a[mt][1], a[mt][2], a[mt][3], aB + aOffAct[mt] + ks * 32);
#pragma unroll
            for (int nt2 = 0; nt2 < 4; nt2++)
                ldsm4(b[nt2][0], b[nt2][1], b[nt2][2], b[nt2][3], bB + bOffW[nt2] + ks * 32);
#pragma unroll
            for (int mt = 0; mt < 2; mt++)
#pragma unroll
                for (int nt2 = 0; nt2 < 4; nt2++) {
                    mma16816(acc[mt][nt2 * 2 + 0], a[mt], b[nt2][0], b[nt2][1]);
                    mma16816(acc[mt][nt2 * 2 + 1], a[mt], b[nt2][2], b[nt2][3]);
                }
        }
    };

    // ================= layer 0: 12 chunks — R12 pipeline verbatim =================
    __syncthreads();                 // misc tables visible
    PFA(0); PFB(0);                  // groups 0,1
    PFA(1); PFB(1);                  // groups 2,3
    CPW(2);                          // A(0), B(0) complete
    __syncthreads();                 // publish staged A(0)/B(0)
    CONV(0);                         // A16[0]; published by bar in iter 0

#pragma unroll 1
    for (int cg = 0; cg < 12; cg++) {
        // Outstanding at entry: B(cg), A(cg+1), B(cg+1). CPW(1) completes B(cg), A(cg+1).
        CPW(1);
        __syncthreads();             // publish cp.async data + last iter's CONV stores

        if (cg + 1 < 12) CONV(cg + 1);
        PFA(cg + 2);                 // empty group when cg+2 >= 12
        PFB(cg + 2);                 // empty group when cg+2 >= 12

        const uint32_t aB = sbase + A16_BASE + (cg & 1) * A16_BYTES;
        const uint32_t bB = sbase + B_BASE + (cg % 3) * BB_BYTES;
#pragma unroll
        for (int ks = 0; ks < 2; ks++) {
            uint32_t a[2][4], b[4][4];
#pragma unroll
            for (int mt = 0; mt < 2; mt++)
                ldsm4(a[mt][0], a[mt][1], a[mt][2], a[mt][3], aB + aOff80[mt] + ks * 32);
#pragma unroll
            for (int nt2 = 0; nt2 < 4; nt2++)
                ldsm4(b[nt2][0], b[nt2][1], b[nt2][2], b[nt2][3], bB + bOff80[nt2] + ks * 32);
#pragma unroll
            for (int mt = 0; mt < 2; mt++)
#pragma unroll
                for (int nt2 = 0; nt2 < 4; nt2++) {
                    mma16816(acc[mt][nt2 * 2 + 0], a[mt], b[nt2][0], b[nt2][1]);
                    mma16816(acc[mt][nt2 * 2 + 1], a[mt], b[nt2][2], b[nt2][3]);
                }
        }
    }

    // ================= EPI0 (+ W1 load overlap) + GEMM1 =================
    __syncthreads();                 // MMA(11) reads done: STG, A16, B ring all dead
    LOADW(g_W1h);                    // W1 -> WBUF (aliases A16/B; safe post-bar)
    EPI(true);                       // writes ACT (aliases STG; dead)
    CPW(0);                          // W1 complete (+ leftover empty groups)
    __syncthreads();                 // publish ACT + W1

    GEMM12();                        // layer 1: K=128, W1 resident

    __syncthreads();                 // GEMM1 reads of ACT/WBUF done
    LOADW(g_W2h);                    // W2 -> WBUF
    EPI(false);                      // rewrite ACT
    CPW(0);
    __syncthreads();                 // publish ACT + W2

    GEMM12();                        // layer 2: K=128, W2 resident

    // ================= final epilogue: + b2', relu, BN2 affine, store =================
    const int Ev = E - ebase;
#pragma unroll
    for (int mt = 0; mt < 2; mt++) {
#pragma unroll
        for (int nt = 0; nt < 8; nt++) {
            const int col = cbase + nt * 8 + 2 * tig;
            const float bx = sB2[col], by = sB2[col + 1];
            const float axm = sA2[col], aym = sA2[col + 1];
            const float cxm = sC2[col], cym = sC2[col + 1];
#pragma unroll
            for (int rh = 0; rh < 2; rh++) {
                const int row = rbase + mt * 16 + gid + rh * 8;
                if (row < Ev) {
                    float* c4 = acc[mt][nt];
                    float2 v;
                    v.x = fmaxf(c4[rh * 2 + 0] + bx, 0.f) * axm + cxm;
                    v.y = fmaxf(c4[rh * 2 + 1] + by, 0.f) * aym + cym;
                    *(float2*)&out[(size_t)(ebase + row) * 128 + col] = v;
                }
            }
        }
    }
}

// ---------------- launch ----------------
extern "C" void kernel_launch(void* const* d_in, const int* in_sizes, int n_in,
                              void* d_out, int out_size) {
    const float* src  = (const float*)d_in[0];
    const float* dest = (const float*)d_in[1];
    const float* edge = (const float*)d_in[2];
    const float* u    = (const float*)d_in[3];
    const int*   batch = (const int*)d_in[4];
    const float* W0 = (const float*)d_in[5];
    const float* b0 = (const float*)d_in[6];
    const float* W1 = (const float*)d_in[7];
    const float* b1 = (const float*)d_in[8];
    const float* W2 = (const float*)d_in[9];
    const float* b2 = (const float*)d_in[10];
    const float* g0 = (const float*)d_in[11];
    const float* be0 = (const float*)d_in[12];
    const float* m0 = (const float*)d_in[13];
    const float* v0 = (const float*)d_in[14];
    const float* g1 = (const float*)d_in[15];
    const float* be1 = (const float*)d_in[16];
    const float* m1 = (const float*)d_in[17];
    const float* v1 = (const float*)d_in[18];
    const float* g2 = (const float*)d_in[19];
    const float* be2 = (const float*)d_in[20];
    const float* m2 = (const float*)d_in[21];
    const float* v2 = (const float*)d_in[22];

    int E = in_sizes[0] / 128;

    cudaFuncSetAttribute(megnet_main, cudaFuncAttributeMaxDynamicSharedMemorySize, SMEM_BYTES);

    prep_all<<<512, 256>>>(W0, b0, W1, b1, W2, b2, u,
                           g0, be0, m0, v0, g1, be1, m1, v1, g2, be2, m2, v2);
    megnet_main<<<(E + 127) / 128, 256, SMEM_BYTES>>>(src, dest, edge, batch, (float*)d_out, E);
}